// round 1
// baseline (speedup 1.0000x reference)
#include <cuda_runtime.h>
#include <cstdint>

#define BB 256
#define TT 4096
#define DD 3
#define UU 8

// Scratch (allocation-free rule: __device__ globals)
__device__ float g_xp[BB * TT * 24];   // pre-scaled gate pre-activations from x (+bias)
__device__ float g_f [BB * TT * UU];   // precomputed sigmoid forget gate

// ---------------------------------------------------------------------------
// Kernel 1: xp[b][t][j] = scale_j * (x_t · W[:,j] + b_j)
// j in [0,8): i-gate (scale 0.5), [8,16): c_hat (scale 1), [16,24): o-gate (0.5)
// 0.5 prescale so all gates go through a uniform tanh: sigmoid(x)=0.5*tanh(0.5x)+0.5
// ---------------------------------------------------------------------------
__global__ void xp_kernel(const float* __restrict__ x,
                          const float* __restrict__ W,
                          const float* __restrict__ bias)
{
    int gid = blockIdx.x * blockDim.x + threadIdx.x;
    const int total = BB * TT * 24;
    if (gid >= total) return;
    int j    = gid % 24;
    int item = gid / 24;
    float x0 = __ldg(x + (size_t)item * 3 + 0);
    float x1 = __ldg(x + (size_t)item * 3 + 1);
    float x2 = __ldg(x + (size_t)item * 3 + 2);
    float w0 = __ldg(W + j), w1 = __ldg(W + 24 + j), w2 = __ldg(W + 48 + j);
    float bj, scale;
    if (j < 8)       { bj = __ldg(bias + j);           scale = 0.5f; }  // b_i
    else if (j < 16) { bj = __ldg(bias + 16 + (j-8));  scale = 1.0f; }  // b_c
    else             { bj = __ldg(bias + 24 + (j-16)); scale = 0.5f; }  // b_o
    g_xp[gid] = scale * (x0*w0 + x1*w1 + x2*w2 + bj);
}

// ---------------------------------------------------------------------------
// Kernel 2: signature forget gate.
// Key: L1_{k-1} = p_k - p_0 is pointwise, so the Chen step term
//   M_k[a][b] = (p_k - p_0)[a]*dx_k[b] + 0.5*dx_k[a]*dx_k[b] = s_a * dx_b
// is pointwise, and L2 = cumsum_k(M) is a linear 16-channel prefix sum.
// One block per batch: 256 threads x 16 steps, block scan of 16 channels,
// then project with F (shared) and sigmoid.
// ---------------------------------------------------------------------------
__global__ __launch_bounds__(256) void sigf_kernel(const float* __restrict__ x,
                                                   const float* __restrict__ F,
                                                   const float* __restrict__ bias)
{
    __shared__ float sF[21 * UU];        // forget_kernel (21,8) row-major
    __shared__ float sbf[UU];            // b_f = bias[8:16]
    __shared__ float warp_pre[8][16];

    int b   = blockIdx.x;
    int tid = threadIdx.x;
    if (tid < 21 * UU) sF[tid] = F[tid];
    if (tid < UU)      sbf[tid] = bias[8 + tid];
    __syncthreads();

    const float* xb = x + (size_t)b * TT * DD;
    const float invTm1 = 1.0f / (float)(TT - 1);
    float p0x = xb[0], p0y = xb[1], p0z = xb[2];

    const int STEPS = 16;
    int k0 = tid * STEPS;

    float C[16];
    #pragma unroll
    for (int i = 0; i < 16; i++) C[i] = 0.f;

    // ---- Phase A: per-thread totals of the 16 L2 channels over its 16 steps
    {
        float px = xb[(size_t)k0*3+0], py = xb[(size_t)k0*3+1], pz = xb[(size_t)k0*3+2];
        #pragma unroll 1
        for (int r = 0; r < STEPS; r++) {
            int k = k0 + r;
            if (k < TT - 1) {
                float nx = xb[(size_t)(k+1)*3+0], ny = xb[(size_t)(k+1)*3+1], nz = xb[(size_t)(k+1)*3+2];
                float dx0 = invTm1, dx1 = nx - px, dx2 = ny - py, dx3 = nz - pz;
                float s0 = (float)k * invTm1 + 0.5f * invTm1;
                float s1 = (px - p0x) + 0.5f * dx1;
                float s2 = (py - p0y) + 0.5f * dx2;
                float s3 = (pz - p0z) + 0.5f * dx3;
                C[ 0] += s0*dx0; C[ 1] += s0*dx1; C[ 2] += s0*dx2; C[ 3] += s0*dx3;
                C[ 4] += s1*dx0; C[ 5] += s1*dx1; C[ 6] += s1*dx2; C[ 7] += s1*dx3;
                C[ 8] += s2*dx0; C[ 9] += s2*dx1; C[10] += s2*dx2; C[11] += s2*dx3;
                C[12] += s3*dx0; C[13] += s3*dx1; C[14] += s3*dx2; C[15] += s3*dx3;
                px = nx; py = ny; pz = nz;
            }
        }
    }

    // ---- Block exclusive scan of the 16 channels (warp shfl scan + warp fixup)
    float base[16];
    {
        const unsigned mask = 0xffffffffu;
        int lane = tid & 31, warp = tid >> 5;
        float incl[16];
        #pragma unroll
        for (int c = 0; c < 16; c++) {
            float v = C[c];
            #pragma unroll
            for (int off = 1; off < 32; off <<= 1) {
                float o = __shfl_up_sync(mask, v, off);
                if (lane >= off) v += o;
            }
            incl[c] = v;
        }
        if (lane == 31) {
            #pragma unroll
            for (int c = 0; c < 16; c++) warp_pre[warp][c] = incl[c];
        }
        __syncthreads();
        if (tid == 0) {
            float acc[16];
            #pragma unroll
            for (int c = 0; c < 16; c++) acc[c] = 0.f;
            for (int w = 0; w < 8; w++) {
                #pragma unroll
                for (int c = 0; c < 16; c++) {
                    float tmp = warp_pre[w][c];
                    warp_pre[w][c] = acc[c];
                    acc[c] += tmp;
                }
            }
        }
        __syncthreads();
        #pragma unroll
        for (int c = 0; c < 16; c++)
            base[c] = warp_pre[warp][c] + (incl[c] - C[c]);   // exclusive prefix
    }

    // ---- t = 0: sig = (1,0,...,0), no normalization
    if (tid == 0) {
        #pragma unroll
        for (int u = 0; u < UU; u++) {
            float pre = sF[u] + sbf[u];
            g_f[(size_t)b * TT * UU + u] = 1.0f / (1.0f + __expf(-pre));
        }
    }

    // ---- Phase B: rebuild running C (inclusive), project with F, sigmoid, store
    {
        float px = xb[(size_t)k0*3+0], py = xb[(size_t)k0*3+1], pz = xb[(size_t)k0*3+2];
        #pragma unroll 1
        for (int r = 0; r < STEPS; r++) {
            int k = k0 + r;
            if (k < TT - 1) {
                float nx = xb[(size_t)(k+1)*3+0], ny = xb[(size_t)(k+1)*3+1], nz = xb[(size_t)(k+1)*3+2];
                float dx0 = invTm1, dx1 = nx - px, dx2 = ny - py, dx3 = nz - pz;
                float s0 = (float)k * invTm1 + 0.5f * invTm1;
                float s1 = (px - p0x) + 0.5f * dx1;
                float s2 = (py - p0y) + 0.5f * dx2;
                float s3 = (pz - p0z) + 0.5f * dx3;
                base[ 0] += s0*dx0; base[ 1] += s0*dx1; base[ 2] += s0*dx2; base[ 3] += s0*dx3;
                base[ 4] += s1*dx0; base[ 5] += s1*dx1; base[ 6] += s1*dx2; base[ 7] += s1*dx3;
                base[ 8] += s2*dx0; base[ 9] += s2*dx1; base[10] += s2*dx2; base[11] += s2*dx3;
                base[12] += s3*dx0; base[13] += s3*dx1; base[14] += s3*dx2; base[15] += s3*dx3;
                px = nx; py = ny; pz = nz;

                int t = k + 1;
                float tg    = (float)t * invTm1;
                float invtg = (float)(TT - 1) / (float)t;
                float dX = px - p0x, dY = py - p0y, dZ = pz - p0z;  // L1[1..3] at t
                size_t outb = (size_t)b * TT * UU + (size_t)t * UU;
                #pragma unroll
                for (int u = 0; u < UU; u++) {
                    float acc = sF[u] + tg * sF[8+u] + dX * sF[16+u] + dY * sF[24+u] + dZ * sF[32+u];
                    #pragma unroll
                    for (int ab = 0; ab < 16; ab++)
                        acc += base[ab] * sF[(5 + ab) * 8 + u];
                    float pre = acc * invtg + sbf[u];
                    g_f[outb + u] = 1.0f / (1.0f + __expf(-pre));
                }
            }
        }
    }
}

// ---------------------------------------------------------------------------
// Kernel 3: the serial LSTM recurrence. One warp per batch; lane u (mod 8)
// owns unit u fully (i/chat/o dots, c, h). Only cross-lane traffic: h bcast.
// ---------------------------------------------------------------------------
#define USE_TANH_APPROX 0

__device__ __forceinline__ float ftanh(float v)
{
#if USE_TANH_APPROX
    float y; asm("tanh.approx.f32 %0, %1;" : "=f"(y) : "f"(v)); return y;
#else
    // 1 - 2/(exp(2x)+1): saturates correctly at +/-inf without NaN
    float e = __expf(2.0f * v);
    return 1.0f - __fdividef(2.0f, 1.0f + e);
#endif
}

__global__ __launch_bounds__(32, 1) void scan_kernel(const float* __restrict__ rk,
                                                     float* __restrict__ out)
{
    int b    = blockIdx.x;
    int lane = threadIdx.x;
    int u    = lane & 7;            // lanes 8..31 replicate lanes 0..7 (harmless)

    float Ri[8], Rc[8], Ro[8];
    #pragma unroll
    for (int k = 0; k < 8; k++) {
        Ri[k] = 0.5f * __ldg(rk + k*24 + u);
        Rc[k] =        __ldg(rk + k*24 + 8 + u);
        Ro[k] = 0.5f * __ldg(rk + k*24 + 16 + u);
    }

    const float* xpb = g_xp + (size_t)b * TT * 24;
    const float* fb  = g_f  + (size_t)b * TT * UU;
    float*       ob  = out  + (size_t)b * TT * UU;

    float h = 0.f, c = 0.f;

    float cxi[4], cxc[4], cxo[4], cf[4];
    #pragma unroll
    for (int j = 0; j < 4; j++) {
        const float* p = xpb + (size_t)j * 24;
        cxi[j] = p[u]; cxc[j] = p[8+u]; cxo[j] = p[16+u];
        cf[j]  = fb[(size_t)j * 8 + u];
    }

    const int NG = TT / 4;
    for (int g = 0; g < NG; g++) {
        // prefetch next group of 4 steps (clamped) — hides DRAM off the chain
        int gn = (g + 1 < NG) ? (g + 1) : g;
        float nxi[4], nxc[4], nxo[4], nf[4];
        #pragma unroll
        for (int j = 0; j < 4; j++) {
            const float* p = xpb + (size_t)(gn*4 + j) * 24;
            nxi[j] = p[u]; nxc[j] = p[8+u]; nxo[j] = p[16+u];
            nf[j]  = fb[(size_t)(gn*4 + j) * 8 + u];
        }

        #pragma unroll
        for (int j = 0; j < 4; j++) {
            float h0 = __shfl_sync(0xffffffffu, h, 0);
            float h1 = __shfl_sync(0xffffffffu, h, 1);
            float h2 = __shfl_sync(0xffffffffu, h, 2);
            float h3 = __shfl_sync(0xffffffffu, h, 3);
            float h4 = __shfl_sync(0xffffffffu, h, 4);
            float h5 = __shfl_sync(0xffffffffu, h, 5);
            float h6 = __shfl_sync(0xffffffffu, h, 6);
            float h7 = __shfl_sync(0xffffffffu, h, 7);

            // 2-way split dot products for ILP on the dependency chain
            float ai0 = fmaf(Ri[0],h0, cxi[j]); ai0 = fmaf(Ri[1],h1, ai0);
            ai0 = fmaf(Ri[2],h2, ai0);          ai0 = fmaf(Ri[3],h3, ai0);
            float ai1 = Ri[4]*h4;               ai1 = fmaf(Ri[5],h5, ai1);
            ai1 = fmaf(Ri[6],h6, ai1);          ai1 = fmaf(Ri[7],h7, ai1);

            float ac0 = fmaf(Rc[0],h0, cxc[j]); ac0 = fmaf(Rc[1],h1, ac0);
            ac0 = fmaf(Rc[2],h2, ac0);          ac0 = fmaf(Rc[3],h3, ac0);
            float ac1 = Rc[4]*h4;               ac1 = fmaf(Rc[5],h5, ac1);
            ac1 = fmaf(Rc[6],h6, ac1);          ac1 = fmaf(Rc[7],h7, ac1);

            float ao0 = fmaf(Ro[0],h0, cxo[j]); ao0 = fmaf(Ro[1],h1, ao0);
            ao0 = fmaf(Ro[2],h2, ao0);          ao0 = fmaf(Ro[3],h3, ao0);
            float ao1 = Ro[4]*h4;               ao1 = fmaf(Ro[5],h5, ao1);
            ao1 = fmaf(Ro[6],h6, ao1);          ao1 = fmaf(Ro[7],h7, ao1);

            float ti  = ftanh(ai0 + ai1);   // sigmoid(g_i) = 0.5*ti + 0.5 (prescaled)
            float tch = ftanh(ac0 + ac1);   // tanh(g_c)
            float to  = ftanh(ao0 + ao1);   // sigmoid(g_o) = 0.5*to + 0.5

            float ig = fmaf(ti, 0.5f, 0.5f);
            c = fmaf(cf[j], c, ig * tch);
            float tc = ftanh(c);
            h = fmaf(to, 0.5f, 0.5f) * tc;

            if (lane < 8) ob[(size_t)(g*4 + j) * 8 + u] = h;
        }

        #pragma unroll
        for (int j = 0; j < 4; j++) { cxi[j]=nxi[j]; cxc[j]=nxc[j]; cxo[j]=nxo[j]; cf[j]=nf[j]; }
    }
}

// ---------------------------------------------------------------------------
extern "C" void kernel_launch(void* const* d_in, const int* in_sizes, int n_in,
                              void* d_out, int out_size)
{
    const float* x  = (const float*)d_in[0];   // inputs (B,T,3)
    const float* Wi = (const float*)d_in[1];   // input_kernel (3,24)
    const float* Rk = (const float*)d_in[2];   // recurrent_kernel (8,24)
    const float* Fk = (const float*)d_in[3];   // forget_kernel (21,8)
    const float* bs = (const float*)d_in[4];   // bias (32,)
    float* out = (float*)d_out;

    int total = BB * TT * 24;
    xp_kernel<<<(total + 255) / 256, 256>>>(x, Wi, bs);
    sigf_kernel<<<BB, 256>>>(x, Fk, bs);
    scan_kernel<<<BB, 32>>>(Rk, out);
}

// round 2
// speedup vs baseline: 1.7039x; 1.7039x over previous
#include <cuda_runtime.h>
#include <cstdint>

#define BB 256
#define TT 4096
#define DD 3
#define UU 8

// Scratch (allocation-free rule: __device__ globals)
__device__ float g_f[BB * TT * UU];   // precomputed sigmoid forget gate (b,t,u)

// ---------------------------------------------------------------------------
// Kernel 1: signature forget gate (unchanged from R1 — measured-cheap).
// L1_{k-1} = p_k - p_0 is pointwise; Chen L2 step term is pointwise; L2 is a
// linear 16-channel prefix sum -> block scan. Then project with F + sigmoid.
// ---------------------------------------------------------------------------
__global__ __launch_bounds__(256) void sigf_kernel(const float* __restrict__ x,
                                                   const float* __restrict__ F,
                                                   const float* __restrict__ bias)
{
    __shared__ float sF[21 * UU];
    __shared__ float sbf[UU];
    __shared__ float warp_pre[8][16];

    int b   = blockIdx.x;
    int tid = threadIdx.x;
    if (tid < 21 * UU) sF[tid] = F[tid];
    if (tid < UU)      sbf[tid] = bias[8 + tid];
    __syncthreads();

    const float* xb = x + (size_t)b * TT * DD;
    const float invTm1 = 1.0f / (float)(TT - 1);
    float p0x = xb[0], p0y = xb[1], p0z = xb[2];

    const int STEPS = 16;
    int k0 = tid * STEPS;

    float C[16];
    #pragma unroll
    for (int i = 0; i < 16; i++) C[i] = 0.f;

    // ---- Phase A: per-thread totals of the 16 L2 channels
    {
        float px = xb[(size_t)k0*3+0], py = xb[(size_t)k0*3+1], pz = xb[(size_t)k0*3+2];
        #pragma unroll 1
        for (int r = 0; r < STEPS; r++) {
            int k = k0 + r;
            if (k < TT - 1) {
                float nx = xb[(size_t)(k+1)*3+0], ny = xb[(size_t)(k+1)*3+1], nz = xb[(size_t)(k+1)*3+2];
                float dx0 = invTm1, dx1 = nx - px, dx2 = ny - py, dx3 = nz - pz;
                float s0 = (float)k * invTm1 + 0.5f * invTm1;
                float s1 = (px - p0x) + 0.5f * dx1;
                float s2 = (py - p0y) + 0.5f * dx2;
                float s3 = (pz - p0z) + 0.5f * dx3;
                C[ 0] += s0*dx0; C[ 1] += s0*dx1; C[ 2] += s0*dx2; C[ 3] += s0*dx3;
                C[ 4] += s1*dx0; C[ 5] += s1*dx1; C[ 6] += s1*dx2; C[ 7] += s1*dx3;
                C[ 8] += s2*dx0; C[ 9] += s2*dx1; C[10] += s2*dx2; C[11] += s2*dx3;
                C[12] += s3*dx0; C[13] += s3*dx1; C[14] += s3*dx2; C[15] += s3*dx3;
                px = nx; py = ny; pz = nz;
            }
        }
    }

    // ---- Block exclusive scan of the 16 channels
    float base[16];
    {
        const unsigned mask = 0xffffffffu;
        int lane = tid & 31, warp = tid >> 5;
        float incl[16];
        #pragma unroll
        for (int c = 0; c < 16; c++) {
            float v = C[c];
            #pragma unroll
            for (int off = 1; off < 32; off <<= 1) {
                float o = __shfl_up_sync(mask, v, off);
                if (lane >= off) v += o;
            }
            incl[c] = v;
        }
        if (lane == 31) {
            #pragma unroll
            for (int c = 0; c < 16; c++) warp_pre[warp][c] = incl[c];
        }
        __syncthreads();
        if (tid == 0) {
            float acc[16];
            #pragma unroll
            for (int c = 0; c < 16; c++) acc[c] = 0.f;
            for (int w = 0; w < 8; w++) {
                #pragma unroll
                for (int c = 0; c < 16; c++) {
                    float tmp = warp_pre[w][c];
                    warp_pre[w][c] = acc[c];
                    acc[c] += tmp;
                }
            }
        }
        __syncthreads();
        #pragma unroll
        for (int c = 0; c < 16; c++)
            base[c] = warp_pre[warp][c] + (incl[c] - C[c]);
    }

    // ---- t = 0
    if (tid == 0) {
        #pragma unroll
        for (int u = 0; u < UU; u++) {
            float pre = sF[u] + sbf[u];
            g_f[(size_t)b * TT * UU + u] = 1.0f / (1.0f + __expf(-pre));
        }
    }

    // ---- Phase B: inclusive rebuild, project, sigmoid, store
    {
        float px = xb[(size_t)k0*3+0], py = xb[(size_t)k0*3+1], pz = xb[(size_t)k0*3+2];
        #pragma unroll 1
        for (int r = 0; r < STEPS; r++) {
            int k = k0 + r;
            if (k < TT - 1) {
                float nx = xb[(size_t)(k+1)*3+0], ny = xb[(size_t)(k+1)*3+1], nz = xb[(size_t)(k+1)*3+2];
                float dx0 = invTm1, dx1 = nx - px, dx2 = ny - py, dx3 = nz - pz;
                float s0 = (float)k * invTm1 + 0.5f * invTm1;
                float s1 = (px - p0x) + 0.5f * dx1;
                float s2 = (py - p0y) + 0.5f * dx2;
                float s3 = (pz - p0z) + 0.5f * dx3;
                base[ 0] += s0*dx0; base[ 1] += s0*dx1; base[ 2] += s0*dx2; base[ 3] += s0*dx3;
                base[ 4] += s1*dx0; base[ 5] += s1*dx1; base[ 6] += s1*dx2; base[ 7] += s1*dx3;
                base[ 8] += s2*dx0; base[ 9] += s2*dx1; base[10] += s2*dx2; base[11] += s2*dx3;
                base[12] += s3*dx0; base[13] += s3*dx1; base[14] += s3*dx2; base[15] += s3*dx3;
                px = nx; py = ny; pz = nz;

                int t = k + 1;
                float tg    = (float)t * invTm1;
                float invtg = (float)(TT - 1) / (float)t;
                float dX = px - p0x, dY = py - p0y, dZ = pz - p0z;
                size_t outb = (size_t)b * TT * UU + (size_t)t * UU;
                #pragma unroll
                for (int u = 0; u < UU; u++) {
                    float acc = sF[u] + tg * sF[8+u] + dX * sF[16+u] + dY * sF[24+u] + dZ * sF[32+u];
                    #pragma unroll
                    for (int ab = 0; ab < 16; ab++)
                        acc += base[ab] * sF[(5 + ab) * 8 + u];
                    float pre = acc * invtg + sbf[u];
                    g_f[outb + u] = 1.0f / (1.0f + __expf(-pre));
                }
            }
        }
    }
}

// ---------------------------------------------------------------------------
// Kernel 2: serial LSTM recurrence.
//   - 4 batches per warp (lane groups of 8, width-8 shuffles) -> 64 blocks,
//     ONE wave on 148 SMs (R1 ran 2 waves = 2x serial time).
//   - tanh.approx.f32 (1 MUFU) instead of exp-based tanh (2 MUFU + 3 ALU):
//     critical path 154 -> ~90 cyc/step. rel_err headroom (4e-6 vs 1e-3) pays.
//   - x-projection fused (was a separate 70us kernel + 200MB DRAM round-trip).
// ---------------------------------------------------------------------------
__device__ __forceinline__ float ftanh(float v)
{
    float y;
    asm("tanh.approx.f32 %0, %1;" : "=f"(y) : "f"(v));
    return y;
}

__global__ __launch_bounds__(32, 1) void scan_kernel(const float* __restrict__ x,
                                                     const float* __restrict__ rk,
                                                     const float* __restrict__ W,
                                                     const float* __restrict__ bias,
                                                     float* __restrict__ out)
{
    const unsigned FULL = 0xffffffffu;
    int lane = threadIdx.x;
    int grp  = lane >> 3;          // 0..3 : batch within warp
    int u    = lane & 7;           // unit
    int b    = blockIdx.x * 4 + grp;

    // Recurrent weights, i/o columns pre-scaled by 0.5 so every nonlinearity is
    // a uniform tanh: sigmoid(g) = 0.5*tanh(0.5*g) + 0.5
    float Ri[8], Rc[8], Ro[8];
    #pragma unroll
    for (int k = 0; k < 8; k++) {
        Ri[k] = 0.5f * __ldg(rk + k*24 + u);
        Rc[k] =        __ldg(rk + k*24 + 8 + u);
        Ro[k] = 0.5f * __ldg(rk + k*24 + 16 + u);
    }
    // Input-projection columns + biases (same prescale)
    float wi0 = 0.5f*__ldg(W + u),      wi1 = 0.5f*__ldg(W + 24 + u),      wi2 = 0.5f*__ldg(W + 48 + u);
    float wc0 =       __ldg(W + 8 + u), wc1 =       __ldg(W + 24 + 8 + u), wc2 =       __ldg(W + 48 + 8 + u);
    float wo0 = 0.5f*__ldg(W + 16 + u), wo1 = 0.5f*__ldg(W + 24 + 16 + u), wo2 = 0.5f*__ldg(W + 48 + 16 + u);
    float bi  = 0.5f*__ldg(bias + u);          // b_i
    float bc  =       __ldg(bias + 16 + u);    // b_c
    float bo  = 0.5f*__ldg(bias + 24 + u);     // b_o

    const float* xb = x   + (size_t)b * TT * 3;
    const float* fb = g_f + (size_t)b * TT * UU;
    float*       ob = out + (size_t)b * TT * UU;

    float h = 0.f, c = 0.f;

    // Prefetch group 0: x (12 contiguous floats = 3 float4) + f (4 scalars)
    float xs[12], fv[4];
    {
        const float4* xp4 = (const float4*)(xb);
        float4 a = __ldg(xp4 + 0), e = __ldg(xp4 + 1), d = __ldg(xp4 + 2);
        xs[0]=a.x; xs[1]=a.y; xs[2]=a.z; xs[3]=a.w;
        xs[4]=e.x; xs[5]=e.y; xs[6]=e.z; xs[7]=e.w;
        xs[8]=d.x; xs[9]=d.y; xs[10]=d.z; xs[11]=d.w;
        #pragma unroll
        for (int j = 0; j < 4; j++) fv[j] = __ldg(fb + (size_t)j * 8 + u);
    }

    const int NG = TT / 4;
    for (int g = 0; g < NG; g++) {
        int gn = (g + 1 < NG) ? (g + 1) : g;
        float nxs[12], nfv[4];
        {
            const float4* xp4 = (const float4*)(xb + (size_t)gn * 12);
            float4 a = __ldg(xp4 + 0), e = __ldg(xp4 + 1), d = __ldg(xp4 + 2);
            nxs[0]=a.x; nxs[1]=a.y; nxs[2]=a.z; nxs[3]=a.w;
            nxs[4]=e.x; nxs[5]=e.y; nxs[6]=e.z; nxs[7]=e.w;
            nxs[8]=d.x; nxs[9]=d.y; nxs[10]=d.z; nxs[11]=d.w;
            #pragma unroll
            for (int j = 0; j < 4; j++) nfv[j] = __ldg(fb + (size_t)(gn*4 + j) * 8 + u);
        }

        #pragma unroll
        for (int j = 0; j < 4; j++) {
            // x-projection for this step (off the serial chain; uses prefetched regs)
            float x0 = xs[3*j+0], x1 = xs[3*j+1], x2 = xs[3*j+2];
            float gi = fmaf(wi2, x2, fmaf(wi1, x1, fmaf(wi0, x0, bi)));
            float gc = fmaf(wc2, x2, fmaf(wc1, x1, fmaf(wc0, x0, bc)));
            float go = fmaf(wo2, x2, fmaf(wo1, x1, fmaf(wo0, x0, bo)));

            // broadcast h within the 8-lane group
            float h0 = __shfl_sync(FULL, h, 0, 8);
            float h1 = __shfl_sync(FULL, h, 1, 8);
            float h2 = __shfl_sync(FULL, h, 2, 8);
            float h3 = __shfl_sync(FULL, h, 3, 8);
            float h4 = __shfl_sync(FULL, h, 4, 8);
            float h5 = __shfl_sync(FULL, h, 5, 8);
            float h6 = __shfl_sync(FULL, h, 6, 8);
            float h7 = __shfl_sync(FULL, h, 7, 8);

            // 2-way split dots for chain ILP
            float ai0 = fmaf(Ri[0],h0, gi);  ai0 = fmaf(Ri[1],h1, ai0);
            ai0 = fmaf(Ri[2],h2, ai0);       ai0 = fmaf(Ri[3],h3, ai0);
            float ai1 = Ri[4]*h4;            ai1 = fmaf(Ri[5],h5, ai1);
            ai1 = fmaf(Ri[6],h6, ai1);       ai1 = fmaf(Ri[7],h7, ai1);

            float ac0 = fmaf(Rc[0],h0, gc);  ac0 = fmaf(Rc[1],h1, ac0);
            ac0 = fmaf(Rc[2],h2, ac0);       ac0 = fmaf(Rc[3],h3, ac0);
            float ac1 = Rc[4]*h4;            ac1 = fmaf(Rc[5],h5, ac1);
            ac1 = fmaf(Rc[6],h6, ac1);       ac1 = fmaf(Rc[7],h7, ac1);

            float ao0 = fmaf(Ro[0],h0, go);  ao0 = fmaf(Ro[1],h1, ao0);
            ao0 = fmaf(Ro[2],h2, ao0);       ao0 = fmaf(Ro[3],h3, ao0);
            float ao1 = Ro[4]*h4;            ao1 = fmaf(Ro[5],h5, ao1);
            ao1 = fmaf(Ro[6],h6, ao1);       ao1 = fmaf(Ro[7],h7, ao1);

            float ti  = ftanh(ai0 + ai1);    // sigmoid(i) = 0.5*ti + 0.5
            float tch = ftanh(ac0 + ac1);    // tanh(c_hat)
            float to  = ftanh(ao0 + ao1);    // sigmoid(o) = 0.5*to + 0.5

            float ig = fmaf(ti, 0.5f, 0.5f);
            c = fmaf(fv[j], c, ig * tch);
            float tc = ftanh(c);
            h = fmaf(to, 0.5f, 0.5f) * tc;

            ob[(size_t)(g*4 + j) * 8 + u] = h;
        }

        #pragma unroll
        for (int j = 0; j < 12; j++) xs[j] = nxs[j];
        #pragma unroll
        for (int j = 0; j < 4; j++)  fv[j] = nfv[j];
    }
}

// ---------------------------------------------------------------------------
extern "C" void kernel_launch(void* const* d_in, const int* in_sizes, int n_in,
                              void* d_out, int out_size)
{
    const float* x  = (const float*)d_in[0];   // inputs (B,T,3)
    const float* Wi = (const float*)d_in[1];   // input_kernel (3,24)
    const float* Rk = (const float*)d_in[2];   // recurrent_kernel (8,24)
    const float* Fk = (const float*)d_in[3];   // forget_kernel (21,8)
    const float* bs = (const float*)d_in[4];   // bias (32,)
    float* out = (float*)d_out;

    sigf_kernel<<<BB, 256>>>(x, Fk, bs);
    scan_kernel<<<BB/4, 32>>>(x, Rk, Wi, bs, out);
}